// round 11
// baseline (speedup 1.0000x reference)
#include <cuda_runtime.h>
#include <cuda_bf16.h>

#define N_NODES 100000
#define N_EDGES 3200000
#define N_GRAPHS 256
// DIMS: 38 -> 64 -> 32 -> 16

// ---------------- scratch (static device globals; no allocs) ----------------
__device__ float g_x40 [N_NODES * 40];
__device__ float g_agg0[N_NODES * 40];
__device__ float g_agg1[N_NODES * 32];
__device__ float g_agg2[N_NODES * 16];
__device__ float g_h1[N_NODES * 64];
__device__ float g_h2[N_NODES * 32];
__device__ float g_y1[N_NODES * 32];
__device__ float g_y2[N_NODES * 16];
__device__ int   g_src[N_EDGES];
__device__ int   g_dst[N_EDGES];
__device__ float g_pool[N_GRAPHS * 16];
__device__ float g_cnt[N_GRAPHS];
__device__ int   g_ei_is64;
__device__ int   g_b_is64;

__device__ __forceinline__ void red_add_v4(float* addr, float4 v) {
    asm volatile("red.global.add.v4.f32 [%0], {%1,%2,%3,%4};"
                 :: "l"(addr), "f"(v.x), "f"(v.y), "f"(v.z), "f"(v.w)
                 : "memory");
}

// ---------------- dtype detection (int32 vs int64 buffers) ------------------
__global__ void k_detect(const int* __restrict__ ei_raw,
                         const int* __restrict__ b_raw) {
    int nz = 0;
    #pragma unroll
    for (int i = 0; i < 64; i++) nz |= ei_raw[2 * i + 1];
    g_ei_is64 = (nz == 0) ? 1 : 0;
    g_b_is64 = (b_raw[N_NODES - 1] == 0) ? 1 : 0;
}

// ---------------- fused prep: convert indices + zero + pack x ---------------
__global__ void k_prep(const float* __restrict__ x,
                       const int* __restrict__ ei_raw) {
    long long i = (long long)blockIdx.x * blockDim.x + threadIdx.x;
    long long stride = (long long)gridDim.x * blockDim.x;
    int is64 = g_ei_is64;
    for (long long e = i; e < N_EDGES; e += stride) {
        if (is64) {
            g_src[e] = ei_raw[2 * e];
            g_dst[e] = ei_raw[2 * ((long long)N_EDGES + e)];
        } else {
            g_src[e] = ei_raw[e];
            g_dst[e] = ei_raw[N_EDGES + e];
        }
    }
    for (long long k = i; k < (long long)N_NODES * 40; k += stride) {
        g_agg0[k] = 0.f;
        int j = (int)(k % 40);
        g_x40[k] = (j < 38) ? x[(k / 40) * 38 + j] : 0.f;
    }
    for (long long k = i; k < (long long)N_NODES * 32; k += stride) g_agg1[k] = 0.f;
    for (long long k = i; k < (long long)N_NODES * 16; k += stride) g_agg2[k] = 0.f;
    for (long long k = i; k < N_GRAPHS * 16; k += stride) g_pool[k] = 0.f;
    for (long long k = i; k < N_GRAPHS; k += stride) g_cnt[k] = 0.f;
}

// ---------------- scatters (proven at REDG/L1-wavefront floor) --------------
__global__ void k_scatter0() {
    long long idx = (long long)blockIdx.x * blockDim.x + threadIdx.x;
    if (idx >= (long long)N_EDGES * 10) return;
    int e = (int)(idx / 10);
    int c = (int)(idx - (long long)e * 10);
    int s = g_src[e];
    int d = g_dst[e];
    float4 v = *(const float4*)&g_x40[s * 40 + c * 4];
    red_add_v4(&g_agg0[d * 40 + c * 4], v);
}

__global__ void k_scatter1() {
    long long idx = (long long)blockIdx.x * blockDim.x + threadIdx.x;
    if (idx >= (long long)N_EDGES * 8) return;
    int e = (int)(idx >> 3);
    int c = (int)(idx & 7);
    int s = g_src[e];
    int d = g_dst[e];
    float4 v = *(const float4*)&g_y1[s * 32 + c * 4];
    red_add_v4(&g_agg1[d * 32 + c * 4], v);
}

__global__ void k_scatter2() {
    long long idx = (long long)blockIdx.x * blockDim.x + threadIdx.x;
    if (idx >= (long long)N_EDGES * 4) return;
    int e = (int)(idx >> 2);
    int c = (int)(idx & 3);
    int s = g_src[e];
    int d = g_dst[e];
    float4 v = *(const float4*)&g_y2[s * 16 + c * 4];
    red_add_v4(&g_agg2[d * 16 + c * 4], v);
}

// ---------------- node0 phase A: h1 only (activation-stationary) ------------
// lane = node; activations in 80 regs; weight rows are warp-uniform broadcasts.
__global__ void __launch_bounds__(256, 2)
k_node0A(const float* __restrict__ Wr0,  // [64,38]
         const float* __restrict__ b0,   // [64]
         const float* __restrict__ Wt0)  // [64,38]
{
    __shared__ float sWr[64 * 40], sWt[64 * 40], sb0[64];
    int t = threadIdx.x;
    int lane = t & 31, wid = t >> 5;
    for (int i = t; i < 64 * 40; i += 256) {
        int o = i / 40, j = i % 40;
        sWr[i] = (j < 38) ? Wr0[o * 38 + j] : 0.f;
        sWt[i] = (j < 38) ? Wt0[o * 38 + j] : 0.f;
    }
    if (t < 64) sb0[t] = b0[t];
    __syncthreads();

    for (int nbase = blockIdx.x * 256; nbase < N_NODES; nbase += gridDim.x * 256) {
        int node = nbase + wid * 32 + lane;
        bool valid = node < N_NODES;
        int nc = valid ? node : (N_NODES - 1);
        float4 a4[10], x4[10];
        #pragma unroll
        for (int c = 0; c < 10; c++) {
            a4[c] = *(const float4*)&g_agg0[nc * 40 + c * 4];
            x4[c] = *(const float4*)&g_x40 [nc * 40 + c * 4];
        }
        #pragma unroll
        for (int og = 0; og < 16; og++) {
            float hk[4];
            #pragma unroll
            for (int k = 0; k < 4; k++) {
                int o = og * 4 + k;
                float h = sb0[o];
                const float* wr = &sWr[o * 40];
                const float* wt = &sWt[o * 40];
                #pragma unroll
                for (int c = 0; c < 10; c++) {
                    float4 w = *(const float4*)&wr[c * 4];  // broadcast
                    float4 u = *(const float4*)&wt[c * 4];  // broadcast
                    h += w.x*a4[c].x + w.y*a4[c].y + w.z*a4[c].z + w.w*a4[c].w
                       + u.x*x4[c].x + u.y*x4[c].y + u.z*x4[c].z + u.w*x4[c].w;
                }
                hk[k] = tanhf(h);
            }
            if (valid)
                *(float4*)&g_h1[node * 64 + og * 4] =
                    make_float4(hk[0], hk[1], hk[2], hk[3]);
        }
    }
}

// ---------------- node0 phase B: y1 = h1 @ Wr1^T (outer product) ------------
__global__ void __launch_bounds__(256, 2)
k_y1(const float* __restrict__ Wr1)       // [32,64]
{
    __shared__ float sW1T[64 * 32];       // sW1T[o*32+oo] = Wr1[oo][o]
    int t = threadIdx.x;
    int lane = t & 31, wid = t >> 5;
    for (int i = t; i < 64 * 32; i += 256) {
        int o = i >> 5, oo = i & 31;
        sW1T[i] = Wr1[oo * 64 + o];
    }
    __syncthreads();

    for (int nbase = blockIdx.x * 256; nbase < N_NODES; nbase += gridDim.x * 256) {
        int node = nbase + wid * 32 + lane;
        bool valid = node < N_NODES;
        int nc = valid ? node : (N_NODES - 1);
        float4 h4[16];
        #pragma unroll
        for (int c = 0; c < 16; c++)
            h4[c] = *(const float4*)&g_h1[nc * 64 + c * 4];
        float acc[32];
        #pragma unroll
        for (int i = 0; i < 32; i++) acc[i] = 0.f;
        #pragma unroll
        for (int o = 0; o < 64; o++) {
            float4 q = h4[o >> 2];
            int r = o & 3;
            float h = (r == 0) ? q.x : (r == 1) ? q.y : (r == 2) ? q.z : q.w;
            const float* w1 = &sW1T[o * 32];
            #pragma unroll
            for (int c2 = 0; c2 < 8; c2++) {
                float4 wv = *(const float4*)&w1[c2 * 4];  // broadcast
                acc[4*c2+0] += wv.x * h;
                acc[4*c2+1] += wv.y * h;
                acc[4*c2+2] += wv.z * h;
                acc[4*c2+3] += wv.w * h;
            }
        }
        if (valid) {
            #pragma unroll
            for (int c2 = 0; c2 < 8; c2++)
                *(float4*)&g_y1[node * 32 + c2 * 4] =
                    make_float4(acc[4*c2+0], acc[4*c2+1], acc[4*c2+2], acc[4*c2+3]);
        }
    }
}

// ---------------- node kernel 1: 32 nodes/iter, ILP=4 (unchanged) -----------
__global__ void k_node1(const float* __restrict__ b1,   // [32]
                        const float* __restrict__ Wt1,  // [32,64]
                        const float* __restrict__ Wr2)  // [16,32]
{
    int t = threadIdx.x;
    int o = t & 31, sl = t >> 5;
    float wt1[64];
    #pragma unroll
    for (int j = 0; j < 64; j++) wt1[j] = Wt1[o * 64 + j];
    float bias = b1[o];
    int oo = o & 15, jb = (o < 16) ? 0 : 16;

    __shared__ float sW2[16 * 33];
    __shared__ float sh1[32][64];
    __shared__ float sh2[32][32];
    for (int i = t; i < 16 * 32; i += 256) sW2[(i >> 5) * 33 + (i & 31)] = Wr2[i];
    __syncthreads();

    for (int nbase = blockIdx.x * 32; nbase < N_NODES; nbase += gridDim.x * 32) {
        for (int i = t; i < 512; i += 256) {
            int n2 = i >> 4, r = i & 15;
            int nn = nbase + n2;
            if (nn < N_NODES)
                *(float4*)&sh1[n2][r * 4] = *(const float4*)&g_h1[nn * 64 + r * 4];
        }
        __syncthreads();
        float hq[4];
        #pragma unroll
        for (int q = 0; q < 4; q++) {
            int nl = sl + 8 * q, node = nbase + nl;
            float h = bias;
            if (node < N_NODES) h += g_agg1[node * 32 + o];
            #pragma unroll
            for (int c = 0; c < 16; c++) {
                float4 hv = *(const float4*)&sh1[nl][c * 4];
                h += wt1[4*c+0]*hv.x + wt1[4*c+1]*hv.y + wt1[4*c+2]*hv.z + wt1[4*c+3]*hv.w;
            }
            hq[q] = tanhf(h);
        }
        #pragma unroll
        for (int q = 0; q < 4; q++) {
            int nl = sl + 8 * q, node = nbase + nl;
            if (node < N_NODES) g_h2[node * 32 + o] = hq[q];
            sh2[nl][o] = hq[q];
        }
        __syncwarp();
        #pragma unroll
        for (int q = 0; q < 4; q++) {
            int nl = sl + 8 * q, node = nbase + nl;
            float p = 0.f;
            #pragma unroll
            for (int c = 0; c < 4; c++) {
                float4 hv = *(const float4*)&sh2[nl][jb + c * 4];
                const float* wrow = &sW2[oo * 33 + jb + c * 4];
                p += wrow[0]*hv.x + wrow[1]*hv.y + wrow[2]*hv.z + wrow[3]*hv.w;
            }
            float other = __shfl_down_sync(0xffffffffu, p, 16);
            if (node < N_NODES && o < 16) g_y2[node * 16 + o] = p + other;
        }
        __syncthreads();
    }
}

// ---------------- node kernel 2 + pooling (unchanged) -----------------------
__global__ void k_node2_pool(const int* __restrict__ batch_raw,
                             const float* __restrict__ b2,   // [16]
                             const float* __restrict__ Wt2)  // [16,32]
{
    int t = threadIdx.x;
    int o = t & 15, sl = t >> 4;
    float wt2[32];
    #pragma unroll
    for (int j = 0; j < 32; j++) wt2[j] = Wt2[o * 32 + j];
    float bias = b2[o];
    int b_is64 = g_b_is64;

    __shared__ float sh2[64][32];

    for (int nbase = blockIdx.x * 64; nbase < N_NODES; nbase += gridDim.x * 64) {
        for (int i = t; i < 512; i += 256) {
            int n2 = i >> 3, r = i & 7;
            int nn = nbase + n2;
            if (nn < N_NODES)
                *(float4*)&sh2[n2][r * 4] = *(const float4*)&g_h2[nn * 32 + r * 4];
        }
        __syncthreads();
        #pragma unroll
        for (int q = 0; q < 4; q++) {
            int nl = sl + 16 * q, node = nbase + nl;
            if (node < N_NODES) {
                float acc = bias + g_agg2[node * 16 + o];
                #pragma unroll
                for (int c = 0; c < 8; c++) {
                    float4 hv = *(const float4*)&sh2[nl][c * 4];
                    acc += wt2[4*c+0]*hv.x + wt2[4*c+1]*hv.y + wt2[4*c+2]*hv.z + wt2[4*c+3]*hv.w;
                }
                int g = b_is64 ? batch_raw[2 * node] : batch_raw[node];
                atomicAdd(&g_pool[g * 16 + o], acc);
                if (o == 0) atomicAdd(&g_cnt[g], 1.0f);
            }
        }
        __syncthreads();
    }
}

// ---------------- final: out = tanh(pool / max(cnt,1)) ----------------------
__global__ void k_final(float* __restrict__ out) {
    int t = blockIdx.x * blockDim.x + threadIdx.x;
    if (t < N_GRAPHS * 16) {
        int g = t >> 4;
        out[t] = tanhf(g_pool[t] / fmaxf(g_cnt[g], 1.0f));
    }
}

extern "C" void kernel_launch(void* const* d_in, const int* in_sizes, int n_in,
                              void* d_out, int out_size) {
    const float* x         = (const float*)d_in[0];
    const int*   ei_raw    = (const int*)d_in[1];
    const int*   batch_raw = (const int*)d_in[2];
    const float* Wr0 = (const float*)d_in[3];
    const float* b0  = (const float*)d_in[4];
    const float* Wt0 = (const float*)d_in[5];
    const float* Wr1 = (const float*)d_in[6];
    const float* b1  = (const float*)d_in[7];
    const float* Wt1 = (const float*)d_in[8];
    const float* Wr2 = (const float*)d_in[9];
    const float* b2  = (const float*)d_in[10];
    const float* Wt2 = (const float*)d_in[11];
    float* out = (float*)d_out;

    k_detect<<<1, 1>>>(ei_raw, batch_raw);
    k_prep<<<2048, 256>>>(x, ei_raw);
    // layer 0
    k_scatter0<<<(int)(((long long)N_EDGES * 10 + 255) / 256), 256>>>();
    k_node0A<<<296, 256>>>(Wr0, b0, Wt0);
    k_y1<<<296, 256>>>(Wr1);
    // layer 1
    k_scatter1<<<(int)(((long long)N_EDGES * 8 + 255) / 256), 256>>>();
    k_node1<<<296, 256>>>(b1, Wt1, Wr2);
    // layer 2
    k_scatter2<<<(int)(((long long)N_EDGES * 4 + 255) / 256), 256>>>();
    k_node2_pool<<<296, 256>>>(batch_raw, b2, Wt2);
    k_final<<<16, 256>>>(out);
}

// round 12
// speedup vs baseline: 1.3184x; 1.3184x over previous
#include <cuda_runtime.h>
#include <cuda_bf16.h>

#define N_NODES 100000
#define N_EDGES 3200000
#define N_GRAPHS 256
// DIMS: 38 -> 64 -> 32 -> 16

// ---------------- scratch (static device globals; no allocs) ----------------
__device__ float g_x40 [N_NODES * 40];
__device__ float g_agg0[N_NODES * 40];
__device__ float g_agg1[N_NODES * 32];
__device__ float g_agg2[N_NODES * 16];
__device__ float g_h1[N_NODES * 64];
__device__ float g_h2[N_NODES * 32];
__device__ float g_y1[N_NODES * 32];
__device__ float g_y2[N_NODES * 16];
__device__ int   g_src[N_EDGES];
__device__ int   g_dst[N_EDGES];
__device__ float g_pool[N_GRAPHS * 16];
__device__ float g_cnt[N_GRAPHS];
__device__ int   g_ei_is64;
__device__ int   g_b_is64;

__device__ __forceinline__ void red_add_v4(float* addr, float4 v) {
    asm volatile("red.global.add.v4.f32 [%0], {%1,%2,%3,%4};"
                 :: "l"(addr), "f"(v.x), "f"(v.y), "f"(v.z), "f"(v.w)
                 : "memory");
}

// ---------------- dtype detection (int32 vs int64 buffers) ------------------
__global__ void k_detect(const int* __restrict__ ei_raw,
                         const int* __restrict__ b_raw) {
    int nz = 0;
    #pragma unroll
    for (int i = 0; i < 64; i++) nz |= ei_raw[2 * i + 1];
    g_ei_is64 = (nz == 0) ? 1 : 0;
    g_b_is64 = (b_raw[N_NODES - 1] == 0) ? 1 : 0;
}

// ---------------- fused prep: convert indices + zero + pack x ---------------
__global__ void k_prep(const float* __restrict__ x,
                       const int* __restrict__ ei_raw) {
    long long i = (long long)blockIdx.x * blockDim.x + threadIdx.x;
    long long stride = (long long)gridDim.x * blockDim.x;
    int is64 = g_ei_is64;
    for (long long e = i; e < N_EDGES; e += stride) {
        if (is64) {
            g_src[e] = ei_raw[2 * e];
            g_dst[e] = ei_raw[2 * ((long long)N_EDGES + e)];
        } else {
            g_src[e] = ei_raw[e];
            g_dst[e] = ei_raw[N_EDGES + e];
        }
    }
    for (long long k = i; k < (long long)N_NODES * 40; k += stride) {
        g_agg0[k] = 0.f;
        int j = (int)(k % 40);
        g_x40[k] = (j < 38) ? x[(k / 40) * 38 + j] : 0.f;
    }
    for (long long k = i; k < (long long)N_NODES * 32; k += stride) g_agg1[k] = 0.f;
    for (long long k = i; k < (long long)N_NODES * 16; k += stride) g_agg2[k] = 0.f;
    for (long long k = i; k < N_GRAPHS * 16; k += stride) g_pool[k] = 0.f;
    for (long long k = i; k < N_GRAPHS; k += stride) g_cnt[k] = 0.f;
}

// ---------------- scatters (proven at REDG/L2-byte floor) -------------------
__global__ void k_scatter0() {
    long long idx = (long long)blockIdx.x * blockDim.x + threadIdx.x;
    if (idx >= (long long)N_EDGES * 10) return;
    int e = (int)(idx / 10);
    int c = (int)(idx - (long long)e * 10);
    int s = g_src[e];
    int d = g_dst[e];
    float4 v = *(const float4*)&g_x40[s * 40 + c * 4];
    red_add_v4(&g_agg0[d * 40 + c * 4], v);
}

__global__ void k_scatter1() {
    long long idx = (long long)blockIdx.x * blockDim.x + threadIdx.x;
    if (idx >= (long long)N_EDGES * 8) return;
    int e = (int)(idx >> 3);
    int c = (int)(idx & 7);
    int s = g_src[e];
    int d = g_dst[e];
    float4 v = *(const float4*)&g_y1[s * 32 + c * 4];
    red_add_v4(&g_agg1[d * 32 + c * 4], v);
}

__global__ void k_scatter2() {
    long long idx = (long long)blockIdx.x * blockDim.x + threadIdx.x;
    if (idx >= (long long)N_EDGES * 4) return;
    int e = (int)(idx >> 2);
    int c = (int)(idx & 3);
    int s = g_src[e];
    int d = g_dst[e];
    float4 v = *(const float4*)&g_y2[s * 16 + c * 4];
    red_add_v4(&g_agg2[d * 16 + c * 4], v);
}

// ---------------- node kernel 0: 16 nodes/iter, ILP=4, 2 blocks/SM ----------
// thread: o = t&63 (output), sl = t>>6 (4 slots); node nl = sl + 4q, q<4.
__global__ void __launch_bounds__(256, 2)
k_node0(const float* __restrict__ Wr0,  // [64,38]
        const float* __restrict__ b0,   // [64]
        const float* __restrict__ Wt0,  // [64,38]
        const float* __restrict__ Wr1)  // [32,64]
{
    int t = threadIdx.x;
    int o = t & 63, sl = t >> 6;
    float wr[40], wt[40];
    #pragma unroll
    for (int j = 0; j < 40; j++) {
        wr[j] = (j < 38) ? Wr0[o * 38 + j] : 0.f;
        wt[j] = (j < 38) ? Wt0[o * 38 + j] : 0.f;
    }
    float bias = b0[o];
    int oo = o & 31, jb = (o < 32) ? 0 : 32;

    __shared__ float  sW1[32 * 65];          // Wr1 [32x64] row stride 65
    __shared__ float4 sa4[16][10], sx4[16][10];
    __shared__ float  sh[16][64];
    __shared__ float  sp[16][64];
    for (int i = t; i < 32 * 64; i += 256) sW1[(i >> 6) * 65 + (i & 63)] = Wr1[i];
    __syncthreads();

    for (int nbase = blockIdx.x * 16; nbase < N_NODES; nbase += gridDim.x * 16) {
        for (int i = t; i < 320; i += 256) {
            int n2 = i / 20, r = i % 20;
            int nn = nbase + n2;
            if (nn < N_NODES) {
                if (r < 10) sa4[n2][r] = *(const float4*)&g_agg0[nn * 40 + r * 4];
                else        sx4[n2][r - 10] = *(const float4*)&g_x40[nn * 40 + (r - 10) * 4];
            }
        }
        __syncthreads();
        float h0 = bias, h1v = bias, h2v = bias, h3 = bias;
        #pragma unroll
        for (int c = 0; c < 10; c++) {
            float w0 = wr[4*c+0], w1_ = wr[4*c+1], w2_ = wr[4*c+2], w3 = wr[4*c+3];
            float u0 = wt[4*c+0], u1 = wt[4*c+1], u2 = wt[4*c+2], u3 = wt[4*c+3];
            float4 a, xv;
            a = sa4[sl][c];      xv = sx4[sl][c];
            h0 += w0*a.x + w1_*a.y + w2_*a.z + w3*a.w + u0*xv.x + u1*xv.y + u2*xv.z + u3*xv.w;
            a = sa4[sl+4][c];    xv = sx4[sl+4][c];
            h1v += w0*a.x + w1_*a.y + w2_*a.z + w3*a.w + u0*xv.x + u1*xv.y + u2*xv.z + u3*xv.w;
            a = sa4[sl+8][c];    xv = sx4[sl+8][c];
            h2v += w0*a.x + w1_*a.y + w2_*a.z + w3*a.w + u0*xv.x + u1*xv.y + u2*xv.z + u3*xv.w;
            a = sa4[sl+12][c];   xv = sx4[sl+12][c];
            h3 += w0*a.x + w1_*a.y + w2_*a.z + w3*a.w + u0*xv.x + u1*xv.y + u2*xv.z + u3*xv.w;
        }
        h0 = tanhf(h0); h1v = tanhf(h1v); h2v = tanhf(h2v); h3 = tanhf(h3);
        float hq[4] = {h0, h1v, h2v, h3};
        #pragma unroll
        for (int q = 0; q < 4; q++) {
            int nl = sl + 4 * q, node = nbase + nl;
            if (node < N_NODES) g_h1[node * 64 + o] = hq[q];
            sh[nl][o] = hq[q];
        }
        __syncthreads();
        #pragma unroll
        for (int q = 0; q < 4; q++) {
            int nl = sl + 4 * q;
            float p = 0.f;
            #pragma unroll
            for (int c = 0; c < 8; c++) {
                float4 hv = *(const float4*)&sh[nl][jb + c * 4];
                const float* wrow = &sW1[oo * 65 + jb + c * 4];
                p += wrow[0]*hv.x + wrow[1]*hv.y + wrow[2]*hv.z + wrow[3]*hv.w;
            }
            sp[nl][o] = p;
        }
        __syncthreads();
        if (o < 32) {
            #pragma unroll
            for (int q = 0; q < 4; q++) {
                int nl = sl + 4 * q, node = nbase + nl;
                if (node < N_NODES) g_y1[node * 32 + o] = sp[nl][o] + sp[nl][o + 32];
            }
        }
        __syncthreads();
    }
}

// ---------------- node kernel 1: 32 nodes/iter, ILP=4 -----------------------
// thread: o = t&31 (warp per node-slot), sl = t>>5 (8 slots); nl = sl + 8q.
__global__ void k_node1(const float* __restrict__ b1,   // [32]
                        const float* __restrict__ Wt1,  // [32,64]
                        const float* __restrict__ Wr2)  // [16,32]
{
    int t = threadIdx.x;
    int o = t & 31, sl = t >> 5;
    float wt1[64];
    #pragma unroll
    for (int j = 0; j < 64; j++) wt1[j] = Wt1[o * 64 + j];
    float bias = b1[o];
    int oo = o & 15, jb = (o < 16) ? 0 : 16;

    __shared__ float sW2[16 * 33];           // Wr2 [16x32] row stride 33
    __shared__ float sh1[32][64];
    __shared__ float sh2[32][32];
    for (int i = t; i < 16 * 32; i += 256) sW2[(i >> 5) * 33 + (i & 31)] = Wr2[i];
    __syncthreads();

    for (int nbase = blockIdx.x * 32; nbase < N_NODES; nbase += gridDim.x * 32) {
        for (int i = t; i < 512; i += 256) {
            int n2 = i >> 4, r = i & 15;
            int nn = nbase + n2;
            if (nn < N_NODES)
                *(float4*)&sh1[n2][r * 4] = *(const float4*)&g_h1[nn * 64 + r * 4];
        }
        __syncthreads();
        float hq[4];
        #pragma unroll
        for (int q = 0; q < 4; q++) {
            int nl = sl + 8 * q, node = nbase + nl;
            float h = bias;
            if (node < N_NODES) h += g_agg1[node * 32 + o];
            #pragma unroll
            for (int c = 0; c < 16; c++) {
                float4 hv = *(const float4*)&sh1[nl][c * 4];
                h += wt1[4*c+0]*hv.x + wt1[4*c+1]*hv.y + wt1[4*c+2]*hv.z + wt1[4*c+3]*hv.w;
            }
            hq[q] = tanhf(h);
        }
        #pragma unroll
        for (int q = 0; q < 4; q++) {
            int nl = sl + 8 * q, node = nbase + nl;
            if (node < N_NODES) g_h2[node * 32 + o] = hq[q];
            sh2[nl][o] = hq[q];
        }
        __syncwarp();
        #pragma unroll
        for (int q = 0; q < 4; q++) {
            int nl = sl + 8 * q, node = nbase + nl;
            float p = 0.f;
            #pragma unroll
            for (int c = 0; c < 4; c++) {
                float4 hv = *(const float4*)&sh2[nl][jb + c * 4];
                const float* wrow = &sW2[oo * 33 + jb + c * 4];
                p += wrow[0]*hv.x + wrow[1]*hv.y + wrow[2]*hv.z + wrow[3]*hv.w;
            }
            float other = __shfl_down_sync(0xffffffffu, p, 16);
            if (node < N_NODES && o < 16) g_y2[node * 16 + o] = p + other;
        }
        __syncthreads();
    }
}

// ---------------- node kernel 2 + pooling: 64 nodes/iter, ILP=4 -------------
__global__ void k_node2_pool(const int* __restrict__ batch_raw,
                             const float* __restrict__ b2,   // [16]
                             const float* __restrict__ Wt2)  // [16,32]
{
    int t = threadIdx.x;
    int o = t & 15, sl = t >> 4;
    float wt2[32];
    #pragma unroll
    for (int j = 0; j < 32; j++) wt2[j] = Wt2[o * 32 + j];
    float bias = b2[o];
    int b_is64 = g_b_is64;

    __shared__ float sh2[64][32];

    for (int nbase = blockIdx.x * 64; nbase < N_NODES; nbase += gridDim.x * 64) {
        for (int i = t; i < 512; i += 256) {
            int n2 = i >> 3, r = i & 7;
            int nn = nbase + n2;
            if (nn < N_NODES)
                *(float4*)&sh2[n2][r * 4] = *(const float4*)&g_h2[nn * 32 + r * 4];
        }
        __syncthreads();
        #pragma unroll
        for (int q = 0; q < 4; q++) {
            int nl = sl + 16 * q, node = nbase + nl;
            if (node < N_NODES) {
                float acc = bias + g_agg2[node * 16 + o];
                #pragma unroll
                for (int c = 0; c < 8; c++) {
                    float4 hv = *(const float4*)&sh2[nl][c * 4];
                    acc += wt2[4*c+0]*hv.x + wt2[4*c+1]*hv.y + wt2[4*c+2]*hv.z + wt2[4*c+3]*hv.w;
                }
                int g = b_is64 ? batch_raw[2 * node] : batch_raw[node];
                atomicAdd(&g_pool[g * 16 + o], acc);
                if (o == 0) atomicAdd(&g_cnt[g], 1.0f);
            }
        }
        __syncthreads();
    }
}

// ---------------- final: out = tanh(pool / max(cnt,1)) ----------------------
__global__ void k_final(float* __restrict__ out) {
    int t = blockIdx.x * blockDim.x + threadIdx.x;
    if (t < N_GRAPHS * 16) {
        int g = t >> 4;
        out[t] = tanhf(g_pool[t] / fmaxf(g_cnt[g], 1.0f));
    }
}

extern "C" void kernel_launch(void* const* d_in, const int* in_sizes, int n_in,
                              void* d_out, int out_size) {
    const float* x         = (const float*)d_in[0];
    const int*   ei_raw    = (const int*)d_in[1];
    const int*   batch_raw = (const int*)d_in[2];
    const float* Wr0 = (const float*)d_in[3];
    const float* b0  = (const float*)d_in[4];
    const float* Wt0 = (const float*)d_in[5];
    const float* Wr1 = (const float*)d_in[6];
    const float* b1  = (const float*)d_in[7];
    const float* Wt1 = (const float*)d_in[8];
    const float* Wr2 = (const float*)d_in[9];
    const float* b2  = (const float*)d_in[10];
    const float* Wt2 = (const float*)d_in[11];
    float* out = (float*)d_out;

    k_detect<<<1, 1>>>(ei_raw, batch_raw);
    k_prep<<<2048, 256>>>(x, ei_raw);
    k_scatter0<<<(int)(((long long)N_EDGES * 10 + 255) / 256), 256>>>();
    k_node0<<<592, 256>>>(Wr0, b0, Wt0, Wr1);
    k_scatter1<<<(int)(((long long)N_EDGES * 8 + 255) / 256), 256>>>();
    k_node1<<<296, 256>>>(b1, Wt1, Wr2);
    k_scatter2<<<(int)(((long long)N_EDGES * 4 + 255) / 256), 256>>>();
    k_node2_pool<<<296, 256>>>(batch_raw, b2, Wt2);
    k_final<<<16, 256>>>(out);
}